// round 1
// baseline (speedup 1.0000x reference)
#include <cuda_runtime.h>

#define T_SEQ   2048
#define NB      2
#define NH      16
#define HD      64
#define DMODEL  1024
#define MROWS   (NB * T_SEQ)   // 4096

// ---- scratch (static device globals; no allocation) ----
static __device__ float g_q[NB * NH * T_SEQ * HD];     // [B,H,T,hd]
static __device__ float g_k[NB * NH * T_SEQ * HD];
static __device__ float g_v[NB * NH * T_SEQ * HD];
static __device__ float g_ao[NB * T_SEQ * DMODEL];     // [B,T,D]

// ============================================================================
// SGEMM body: C[128x128 tile] = A[M,K] @ W[K,N] + bias, M=4096, N=K=1024.
// 256 threads, 8x8 per-thread micro-tile, quad-split layout (rows/cols at
// tr*4 and 64+tr*4) so all LDS.128 are conflict-free or broadcast.
// split_heads: write to [B,H,T,hd] layout instead of [M,N].
// ============================================================================
__device__ __forceinline__ void sgemm_body(
    const float* __restrict__ A, const float* __restrict__ W,
    const float* __restrict__ bias, float* __restrict__ C,
    int split_heads)
{
    __shared__ float As[8][128];
    __shared__ float Bs[8][128];

    const int tid = threadIdx.x;
    const int m0 = blockIdx.y * 128;
    const int n0 = blockIdx.x * 128;
    const int N = DMODEL, K = DMODEL;

    const int arow = tid >> 1;          // 0..127
    const int acol = (tid & 1) << 2;    // 0 or 4
    const int brow = tid >> 5;          // 0..7
    const int bcol = (tid & 31) << 2;   // 0..124
    const int tr = tid >> 4;            // 0..15
    const int tc = tid & 15;            // 0..15

    float acc[8][8];
#pragma unroll
    for (int i = 0; i < 8; i++)
#pragma unroll
        for (int j = 0; j < 8; j++) acc[i][j] = 0.0f;

    const float* Aptr = A + (m0 + arow) * K + acol;
    const float* Wptr = W + brow * N + n0 + bcol;

    for (int k0 = 0; k0 < K; k0 += 8) {
        float4 av = *reinterpret_cast<const float4*>(Aptr + k0);
        float4 bv = *reinterpret_cast<const float4*>(Wptr + (long)k0 * N);
        __syncthreads();
        As[acol + 0][arow] = av.x;
        As[acol + 1][arow] = av.y;
        As[acol + 2][arow] = av.z;
        As[acol + 3][arow] = av.w;
        *reinterpret_cast<float4*>(&Bs[brow][bcol]) = bv;
        __syncthreads();
#pragma unroll
        for (int kk = 0; kk < 8; kk++) {
            float a[8], b[8];
            *reinterpret_cast<float4*>(&a[0]) = *reinterpret_cast<const float4*>(&As[kk][tr * 4]);
            *reinterpret_cast<float4*>(&a[4]) = *reinterpret_cast<const float4*>(&As[kk][tr * 4 + 64]);
            *reinterpret_cast<float4*>(&b[0]) = *reinterpret_cast<const float4*>(&Bs[kk][tc * 4]);
            *reinterpret_cast<float4*>(&b[4]) = *reinterpret_cast<const float4*>(&Bs[kk][tc * 4 + 64]);
#pragma unroll
            for (int i = 0; i < 8; i++)
#pragma unroll
                for (int j = 0; j < 8; j++)
                    acc[i][j] = fmaf(a[i], b[j], acc[i][j]);
        }
    }

    // epilogue: bias add + store
#pragma unroll
    for (int ih = 0; ih < 2; ih++) {
#pragma unroll
        for (int ii = 0; ii < 4; ii++) {
            const int i = ih * 4 + ii;
            const int r = m0 + ih * 64 + tr * 4 + ii;
#pragma unroll
            for (int jh = 0; jh < 2; jh++) {
                const int c = n0 + jh * 64 + tc * 4;
                float4 bb = *reinterpret_cast<const float4*>(&bias[c]);
                float4 ov;
                ov.x = acc[i][jh * 4 + 0] + bb.x;
                ov.y = acc[i][jh * 4 + 1] + bb.y;
                ov.z = acc[i][jh * 4 + 2] + bb.z;
                ov.w = acc[i][jh * 4 + 3] + bb.w;
                if (!split_heads) {
                    *reinterpret_cast<float4*>(&C[(long)r * N + c]) = ov;
                } else {
                    // r = b*T + t ; c = h*64 + d  ->  [B,H,T,hd]
                    const int b = r >> 11;
                    const int t = r & (T_SEQ - 1);
                    const int h = c >> 6;
                    const int d = c & 63;
                    const long idx = (((long)(b * NH + h) * T_SEQ + t) * HD + d);
                    *reinterpret_cast<float4*>(&C[idx]) = ov;
                }
            }
        }
    }
}

__global__ void __launch_bounds__(256, 2)
qkv_kernel(const float* __restrict__ x,
           const float* __restrict__ Wq, const float* __restrict__ bq,
           const float* __restrict__ Wk, const float* __restrict__ bk,
           const float* __restrict__ Wv, const float* __restrict__ bv)
{
    const float* W; const float* bias; float* out;
    if (blockIdx.z == 0)      { W = Wq; bias = bq; out = g_q; }
    else if (blockIdx.z == 1) { W = Wk; bias = bk; out = g_k; }
    else                      { W = Wv; bias = bv; out = g_v; }
    sgemm_body(x, W, bias, out, 1);
}

__global__ void __launch_bounds__(256, 2)
out_kernel(const float* __restrict__ Wo, const float* __restrict__ bo,
           float* __restrict__ C)
{
    sgemm_body(g_ao, Wo, bo, C, 0);
}

// ============================================================================
// Flash attention (fp32): q-tile 128, k-tile 128, online softmax.
// smem: Qt [64 d][132] (transposed, pre-scaled), KV shared buffer
//       (Kt [64][132] then V [128][68]), Ss [128][132] for P.
// ============================================================================
#define QT_STRIDE 132
#define V_STRIDE  68
#define ATTN_SMEM_FLOATS (64 * QT_STRIDE + 128 * V_STRIDE + 128 * QT_STRIDE)
#define ATTN_SMEM_BYTES  (ATTN_SMEM_FLOATS * 4)

__global__ void __launch_bounds__(256)
attn_kernel()
{
    extern __shared__ float sm[];
    float* Qt = sm;                                   // 64 x 132
    float* KV = sm + 64 * QT_STRIDE;                  // max(64x132, 128x68) = 8704
    float* Ss = sm + 64 * QT_STRIDE + 128 * V_STRIDE; // 128 x 132

    const int tid = threadIdx.x;
    const int qt = blockIdx.x;   // 0..15
    const int h  = blockIdx.y;   // 0..15
    const int b  = blockIdx.z;   // 0..1
    const int bh = b * NH + h;

    const float* qg  = g_q + ((long)bh * T_SEQ + qt * 128) * HD;
    const float* kgb = g_k + (long)bh * T_SEQ * HD;
    const float* vgb = g_v + (long)bh * T_SEQ * HD;

    // load Q tile transposed (d-major), pre-scaled by hd^-0.5
    {
        const int row = tid >> 1;
        const int dg  = (tid & 1) * 32;
#pragma unroll
        for (int j = 0; j < 8; j++) {
            float4 qv = *reinterpret_cast<const float4*>(&qg[row * HD + dg + j * 4]);
            Qt[(dg + j * 4 + 0) * QT_STRIDE + row] = qv.x * 0.125f;
            Qt[(dg + j * 4 + 1) * QT_STRIDE + row] = qv.y * 0.125f;
            Qt[(dg + j * 4 + 2) * QT_STRIDE + row] = qv.z * 0.125f;
            Qt[(dg + j * 4 + 3) * QT_STRIDE + row] = qv.w * 0.125f;
        }
    }

    const int tr = tid >> 4;   // 0..15
    const int tc = tid & 15;   // 0..15

    float m_i[8], l_i[8], o[8][4];
#pragma unroll
    for (int i = 0; i < 8; i++) {
        m_i[i] = -1e30f;
        l_i[i] = 0.0f;
#pragma unroll
        for (int j = 0; j < 4; j++) o[i][j] = 0.0f;
    }

    const int nkt = qt + 1;
    for (int kt = 0; kt < nkt; kt++) {
        __syncthreads();  // previous PV reads of KV done; Q visible (iter 0)
        // load K tile transposed into KV
        {
            const int row = tid >> 1;
            const int dg  = (tid & 1) * 32;
            const float* kg = kgb + (long)(kt * 128 + row) * HD;
#pragma unroll
            for (int j = 0; j < 8; j++) {
                float4 kv = *reinterpret_cast<const float4*>(&kg[dg + j * 4]);
                KV[(dg + j * 4 + 0) * QT_STRIDE + row] = kv.x;
                KV[(dg + j * 4 + 1) * QT_STRIDE + row] = kv.y;
                KV[(dg + j * 4 + 2) * QT_STRIDE + row] = kv.z;
                KV[(dg + j * 4 + 3) * QT_STRIDE + row] = kv.w;
            }
        }
        __syncthreads();

        // S = Q @ K^T  (128x128, micro 8x8)
        float s[8][8];
#pragma unroll
        for (int i = 0; i < 8; i++)
#pragma unroll
            for (int j = 0; j < 8; j++) s[i][j] = 0.0f;

#pragma unroll 8
        for (int kk = 0; kk < 64; kk++) {
            float a[8], bb[8];
            *reinterpret_cast<float4*>(&a[0])  = *reinterpret_cast<const float4*>(&Qt[kk * QT_STRIDE + tr * 4]);
            *reinterpret_cast<float4*>(&a[4])  = *reinterpret_cast<const float4*>(&Qt[kk * QT_STRIDE + tr * 4 + 64]);
            *reinterpret_cast<float4*>(&bb[0]) = *reinterpret_cast<const float4*>(&KV[kk * QT_STRIDE + tc * 4]);
            *reinterpret_cast<float4*>(&bb[4]) = *reinterpret_cast<const float4*>(&KV[kk * QT_STRIDE + tc * 4 + 64]);
#pragma unroll
            for (int i = 0; i < 8; i++)
#pragma unroll
                for (int j = 0; j < 8; j++)
                    s[i][j] = fmaf(a[i], bb[j], s[i][j]);
        }

        // causal mask (diagonal tile only)
        const bool diag = (kt == qt);
        const int qrow0 = qt * 128;
        const int kcol0 = kt * 128;

        float rmax[8];
#pragma unroll
        for (int i = 0; i < 8; i++) {
            float mx = -1e30f;
            const int qgidx = qrow0 + ((i & 4) << 4) + tr * 4 + (i & 3);
#pragma unroll
            for (int j = 0; j < 8; j++) {
                if (diag) {
                    const int kgidx = kcol0 + ((j & 4) << 4) + tc * 4 + (j & 3);
                    if (kgidx > qgidx) s[i][j] = -1e30f;
                }
                mx = fmaxf(mx, s[i][j]);
            }
            rmax[i] = mx;
        }
        // row reduce (16 col-threads per row, aligned half-warp groups)
#pragma unroll
        for (int off = 8; off > 0; off >>= 1)
#pragma unroll
            for (int i = 0; i < 8; i++)
                rmax[i] = fmaxf(rmax[i], __shfl_xor_sync(0xffffffffu, rmax[i], off, 16));

#pragma unroll
        for (int i = 0; i < 8; i++) {
            const float mnew  = fmaxf(m_i[i], rmax[i]);
            const float alpha = __expf(m_i[i] - mnew);
            m_i[i] = mnew;
            float rsum = 0.0f;
#pragma unroll
            for (int j = 0; j < 8; j++) {
                s[i][j] = __expf(s[i][j] - mnew);
                rsum += s[i][j];
            }
#pragma unroll
            for (int off = 8; off > 0; off >>= 1)
                rsum += __shfl_xor_sync(0xffffffffu, rsum, off, 16);
            l_i[i] = l_i[i] * alpha + rsum;
#pragma unroll
            for (int j = 0; j < 4; j++) o[i][j] *= alpha;

            const int rl = ((i & 4) << 4) + tr * 4 + (i & 3);
            *reinterpret_cast<float4*>(&Ss[rl * QT_STRIDE + tc * 4]) =
                make_float4(s[i][0], s[i][1], s[i][2], s[i][3]);
            *reinterpret_cast<float4*>(&Ss[rl * QT_STRIDE + 64 + tc * 4]) =
                make_float4(s[i][4], s[i][5], s[i][6], s[i][7]);
        }

        __syncthreads();  // S-compute reads of KV done; Ss stores done

        // load V tile into KV as [128][V_STRIDE]
        {
            const int row = tid >> 1;
            const int dg  = (tid & 1) * 32;
            const float* vg = vgb + (long)(kt * 128 + row) * HD;
#pragma unroll
            for (int j = 0; j < 8; j++) {
                float4 vv = *reinterpret_cast<const float4*>(&vg[dg + j * 4]);
                *reinterpret_cast<float4*>(&KV[row * V_STRIDE + dg + j * 4]) = vv;
            }
        }
        __syncthreads();

        // O += P @ V : per-thread 8 rows x 4 d-cols
#pragma unroll 4
        for (int kk = 0; kk < 128; kk += 4) {
            float4 p4[8];
#pragma unroll
            for (int i = 0; i < 8; i++) {
                const int rl = ((i & 4) << 4) + tr * 4 + (i & 3);
                p4[i] = *reinterpret_cast<const float4*>(&Ss[rl * QT_STRIDE + kk]);
            }
#pragma unroll
            for (int e = 0; e < 4; e++) {
                float4 vv = *reinterpret_cast<const float4*>(&KV[(kk + e) * V_STRIDE + tc * 4]);
#pragma unroll
                for (int i = 0; i < 8; i++) {
                    const float p = reinterpret_cast<const float*>(&p4[i])[e];
                    o[i][0] = fmaf(p, vv.x, o[i][0]);
                    o[i][1] = fmaf(p, vv.y, o[i][1]);
                    o[i][2] = fmaf(p, vv.z, o[i][2]);
                    o[i][3] = fmaf(p, vv.w, o[i][3]);
                }
            }
        }
    }

    // finalize and store to [B,T,D]
#pragma unroll
    for (int i = 0; i < 8; i++) {
        const int rl = ((i & 4) << 4) + tr * 4 + (i & 3);
        const int t = qt * 128 + rl;
        const float inv = 1.0f / l_i[i];
        float4 ov = make_float4(o[i][0] * inv, o[i][1] * inv, o[i][2] * inv, o[i][3] * inv);
        *reinterpret_cast<float4*>(&g_ao[((long)(b * T_SEQ + t)) * DMODEL + h * HD + tc * 4]) = ov;
    }
}

// ============================================================================
extern "C" void kernel_launch(void* const* d_in, const int* in_sizes, int n_in,
                              void* d_out, int out_size)
{
    const float* x  = (const float*)d_in[0];
    const float* Wq = (const float*)d_in[1];
    const float* bq = (const float*)d_in[2];
    const float* Wk = (const float*)d_in[3];
    const float* bk = (const float*)d_in[4];
    const float* Wv = (const float*)d_in[5];
    const float* bv = (const float*)d_in[6];
    const float* Wo = (const float*)d_in[7];
    const float* bo = (const float*)d_in[8];
    float* out = (float*)d_out;

    cudaFuncSetAttribute(attn_kernel,
                         cudaFuncAttributeMaxDynamicSharedMemorySize,
                         ATTN_SMEM_BYTES);

    // QKV projections (fused, grid.z selects weight)
    qkv_kernel<<<dim3(DMODEL / 128, MROWS / 128, 3), 256>>>(x, Wq, bq, Wk, bk, Wv, bv);
    // Flash attention
    attn_kernel<<<dim3(T_SEQ / 128, NH, NB), 256, ATTN_SMEM_BYTES>>>();
    // Output projection
    out_kernel<<<dim3(DMODEL / 128, MROWS / 128), 256>>>(Wo, bo, out);
}

// round 5
// speedup vs baseline: 1.0014x; 1.0014x over previous
#include <cuda_runtime.h>

#define T_SEQ   2048
#define NB      2
#define NH      16
#define HD      64
#define DMODEL  1024
#define MROWS   (NB * T_SEQ)   // 4096

// ---- scratch (static device globals; no allocation) ----
static __device__ float g_q[NB * NH * T_SEQ * HD];     // [B,H,T,hd]
static __device__ float g_k[NB * NH * T_SEQ * HD];
static __device__ float g_v[NB * NH * T_SEQ * HD];
static __device__ float g_ao[NB * T_SEQ * DMODEL];     // [B,T,D]

// ============================================================================
// SGEMM body: C[128x128 tile] = A[M,K] @ W[K,N] + bias, M=4096, N=K=1024.
// 256 threads, 8x8 per-thread micro-tile, quad-split layout (rows/cols at
// tr*4 and 64+tr*4) so all LDS.128 are conflict-free or broadcast.
// split_heads: write to [B,H,T,hd] layout instead of [M,N].
// ============================================================================
__device__ __forceinline__ void sgemm_body(
    const float* __restrict__ A, const float* __restrict__ W,
    const float* __restrict__ bias, float* __restrict__ C,
    int split_heads)
{
    __shared__ float As[8][128];
    __shared__ float Bs[8][128];

    const int tid = threadIdx.x;
    const int m0 = blockIdx.y * 128;
    const int n0 = blockIdx.x * 128;
    const int N = DMODEL, K = DMODEL;

    const int arow = tid >> 1;          // 0..127
    const int acol = (tid & 1) << 2;    // 0 or 4
    const int brow = tid >> 5;          // 0..7
    const int bcol = (tid & 31) << 2;   // 0..124
    const int tr = tid >> 4;            // 0..15
    const int tc = tid & 15;            // 0..15

    float acc[8][8];
#pragma unroll
    for (int i = 0; i < 8; i++)
#pragma unroll
        for (int j = 0; j < 8; j++) acc[i][j] = 0.0f;

    const float* Aptr = A + (m0 + arow) * K + acol;
    const float* Wptr = W + brow * N + n0 + bcol;

    for (int k0 = 0; k0 < K; k0 += 8) {
        float4 av = *reinterpret_cast<const float4*>(Aptr + k0);
        float4 bv = *reinterpret_cast<const float4*>(Wptr + (long)k0 * N);
        __syncthreads();
        As[acol + 0][arow] = av.x;
        As[acol + 1][arow] = av.y;
        As[acol + 2][arow] = av.z;
        As[acol + 3][arow] = av.w;
        *reinterpret_cast<float4*>(&Bs[brow][bcol]) = bv;
        __syncthreads();
#pragma unroll
        for (int kk = 0; kk < 8; kk++) {
            float a[8], b[8];
            *reinterpret_cast<float4*>(&a[0]) = *reinterpret_cast<const float4*>(&As[kk][tr * 4]);
            *reinterpret_cast<float4*>(&a[4]) = *reinterpret_cast<const float4*>(&As[kk][tr * 4 + 64]);
            *reinterpret_cast<float4*>(&b[0]) = *reinterpret_cast<const float4*>(&Bs[kk][tc * 4]);
            *reinterpret_cast<float4*>(&b[4]) = *reinterpret_cast<const float4*>(&Bs[kk][tc * 4 + 64]);
#pragma unroll
            for (int i = 0; i < 8; i++)
#pragma unroll
                for (int j = 0; j < 8; j++)
                    acc[i][j] = fmaf(a[i], b[j], acc[i][j]);
        }
    }

    // epilogue: bias add + store
#pragma unroll
    for (int ih = 0; ih < 2; ih++) {
#pragma unroll
        for (int ii = 0; ii < 4; ii++) {
            const int i = ih * 4 + ii;
            const int r = m0 + ih * 64 + tr * 4 + ii;
#pragma unroll
            for (int jh = 0; jh < 2; jh++) {
                const int c = n0 + jh * 64 + tc * 4;
                float4 bb = *reinterpret_cast<const float4*>(&bias[c]);
                float4 ov;
                ov.x = acc[i][jh * 4 + 0] + bb.x;
                ov.y = acc[i][jh * 4 + 1] + bb.y;
                ov.z = acc[i][jh * 4 + 2] + bb.z;
                ov.w = acc[i][jh * 4 + 3] + bb.w;
                if (!split_heads) {
                    *reinterpret_cast<float4*>(&C[(long)r * N + c]) = ov;
                } else {
                    // r = b*T + t ; c = h*64 + d  ->  [B,H,T,hd]
                    const int b = r >> 11;
                    const int t = r & (T_SEQ - 1);
                    const int h = c >> 6;
                    const int d = c & 63;
                    const long idx = (((long)(b * NH + h) * T_SEQ + t) * HD + d);
                    *reinterpret_cast<float4*>(&C[idx]) = ov;
                }
            }
        }
    }
}

__global__ void __launch_bounds__(256, 2)
qkv_kernel(const float* __restrict__ x,
           const float* __restrict__ Wq, const float* __restrict__ bq,
           const float* __restrict__ Wk, const float* __restrict__ bk,
           const float* __restrict__ Wv, const float* __restrict__ bv)
{
    const float* W; const float* bias; float* out;
    if (blockIdx.z == 0)      { W = Wq; bias = bq; out = g_q; }
    else if (blockIdx.z == 1) { W = Wk; bias = bk; out = g_k; }
    else                      { W = Wv; bias = bv; out = g_v; }
    sgemm_body(x, W, bias, out, 1);
}

__global__ void __launch_bounds__(256, 2)
out_kernel(const float* __restrict__ Wo, const float* __restrict__ bo,
           float* __restrict__ C)
{
    sgemm_body(g_ao, Wo, bo, C, 0);
}

// ============================================================================
// Flash attention (fp32): q-tile 128, k-tile 128, online softmax.
// smem: Qt [64 d][132] (transposed, pre-scaled), KV shared buffer
//       (Kt [64][132] then V [128][68]), Ss [128][132] for P.
// ============================================================================
#define QT_STRIDE 132
#define V_STRIDE  68
#define ATTN_SMEM_FLOATS (64 * QT_STRIDE + 128 * V_STRIDE + 128 * QT_STRIDE)
#define ATTN_SMEM_BYTES  (ATTN_SMEM_FLOATS * 4)

__global__ void __launch_bounds__(256)
attn_kernel()
{
    extern __shared__ float sm[];
    float* Qt = sm;                                   // 64 x 132
    float* KV = sm + 64 * QT_STRIDE;                  // max(64x132, 128x68) = 8704
    float* Ss = sm + 64 * QT_STRIDE + 128 * V_STRIDE; // 128 x 132

    const int tid = threadIdx.x;
    const int qt = blockIdx.x;   // 0..15
    const int h  = blockIdx.y;   // 0..15
    const int b  = blockIdx.z;   // 0..1
    const int bh = b * NH + h;

    const float* qg  = g_q + ((long)bh * T_SEQ + qt * 128) * HD;
    const float* kgb = g_k + (long)bh * T_SEQ * HD;
    const float* vgb = g_v + (long)bh * T_SEQ * HD;

    // load Q tile transposed (d-major), pre-scaled by hd^-0.5
    {
        const int row = tid >> 1;
        const int dg  = (tid & 1) * 32;
#pragma unroll
        for (int j = 0; j < 8; j++) {
            float4 qv = *reinterpret_cast<const float4*>(&qg[row * HD + dg + j * 4]);
            Qt[(dg + j * 4 + 0) * QT_STRIDE + row] = qv.x * 0.125f;
            Qt[(dg + j * 4 + 1) * QT_STRIDE + row] = qv.y * 0.125f;
            Qt[(dg + j * 4 + 2) * QT_STRIDE + row] = qv.z * 0.125f;
            Qt[(dg + j * 4 + 3) * QT_STRIDE + row] = qv.w * 0.125f;
        }
    }

    const int tr = tid >> 4;   // 0..15
    const int tc = tid & 15;   // 0..15

    float m_i[8], l_i[8], o[8][4];
#pragma unroll
    for (int i = 0; i < 8; i++) {
        m_i[i] = -1e30f;
        l_i[i] = 0.0f;
#pragma unroll
        for (int j = 0; j < 4; j++) o[i][j] = 0.0f;
    }

    const int nkt = qt + 1;
    for (int kt = 0; kt < nkt; kt++) {
        __syncthreads();  // previous PV reads of KV done; Q visible (iter 0)
        // load K tile transposed into KV
        {
            const int row = tid >> 1;
            const int dg  = (tid & 1) * 32;
            const float* kg = kgb + (long)(kt * 128 + row) * HD;
#pragma unroll
            for (int j = 0; j < 8; j++) {
                float4 kv = *reinterpret_cast<const float4*>(&kg[dg + j * 4]);
                KV[(dg + j * 4 + 0) * QT_STRIDE + row] = kv.x;
                KV[(dg + j * 4 + 1) * QT_STRIDE + row] = kv.y;
                KV[(dg + j * 4 + 2) * QT_STRIDE + row] = kv.z;
                KV[(dg + j * 4 + 3) * QT_STRIDE + row] = kv.w;
            }
        }
        __syncthreads();

        // S = Q @ K^T  (128x128, micro 8x8)
        float s[8][8];
#pragma unroll
        for (int i = 0; i < 8; i++)
#pragma unroll
            for (int j = 0; j < 8; j++) s[i][j] = 0.0f;

#pragma unroll 8
        for (int kk = 0; kk < 64; kk++) {
            float a[8], bb[8];
            *reinterpret_cast<float4*>(&a[0])  = *reinterpret_cast<const float4*>(&Qt[kk * QT_STRIDE + tr * 4]);
            *reinterpret_cast<float4*>(&a[4])  = *reinterpret_cast<const float4*>(&Qt[kk * QT_STRIDE + tr * 4 + 64]);
            *reinterpret_cast<float4*>(&bb[0]) = *reinterpret_cast<const float4*>(&KV[kk * QT_STRIDE + tc * 4]);
            *reinterpret_cast<float4*>(&bb[4]) = *reinterpret_cast<const float4*>(&KV[kk * QT_STRIDE + tc * 4 + 64]);
#pragma unroll
            for (int i = 0; i < 8; i++)
#pragma unroll
                for (int j = 0; j < 8; j++)
                    s[i][j] = fmaf(a[i], bb[j], s[i][j]);
        }

        // causal mask (diagonal tile only)
        const bool diag = (kt == qt);
        const int qrow0 = qt * 128;
        const int kcol0 = kt * 128;

        float rmax[8];
#pragma unroll
        for (int i = 0; i < 8; i++) {
            float mx = -1e30f;
            const int qgidx = qrow0 + ((i & 4) << 4) + tr * 4 + (i & 3);
#pragma unroll
            for (int j = 0; j < 8; j++) {
                if (diag) {
                    const int kgidx = kcol0 + ((j & 4) << 4) + tc * 4 + (j & 3);
                    if (kgidx > qgidx) s[i][j] = -1e30f;
                }
                mx = fmaxf(mx, s[i][j]);
            }
            rmax[i] = mx;
        }
        // row reduce (16 col-threads per row, aligned half-warp groups)
#pragma unroll
        for (int off = 8; off > 0; off >>= 1)
#pragma unroll
            for (int i = 0; i < 8; i++)
                rmax[i] = fmaxf(rmax[i], __shfl_xor_sync(0xffffffffu, rmax[i], off, 16));

#pragma unroll
        for (int i = 0; i < 8; i++) {
            const float mnew  = fmaxf(m_i[i], rmax[i]);
            const float alpha = __expf(m_i[i] - mnew);
            m_i[i] = mnew;
            float rsum = 0.0f;
#pragma unroll
            for (int j = 0; j < 8; j++) {
                s[i][j] = __expf(s[i][j] - mnew);
                rsum += s[i][j];
            }
#pragma unroll
            for (int off = 8; off > 0; off >>= 1)
                rsum += __shfl_xor_sync(0xffffffffu, rsum, off, 16);
            l_i[i] = l_i[i] * alpha + rsum;
#pragma unroll
            for (int j = 0; j < 4; j++) o[i][j] *= alpha;

            const int rl = ((i & 4) << 4) + tr * 4 + (i & 3);
            *reinterpret_cast<float4*>(&Ss[rl * QT_STRIDE + tc * 4]) =
                make_float4(s[i][0], s[i][1], s[i][2], s[i][3]);
            *reinterpret_cast<float4*>(&Ss[rl * QT_STRIDE + 64 + tc * 4]) =
                make_float4(s[i][4], s[i][5], s[i][6], s[i][7]);
        }

        __syncthreads();  // S-compute reads of KV done; Ss stores done

        // load V tile into KV as [128][V_STRIDE]
        {
            const int row = tid >> 1;
            const int dg  = (tid & 1) * 32;
            const float* vg = vgb + (long)(kt * 128 + row) * HD;
#pragma unroll
            for (int j = 0; j < 8; j++) {
                float4 vv = *reinterpret_cast<const float4*>(&vg[dg + j * 4]);
                *reinterpret_cast<float4*>(&KV[row * V_STRIDE + dg + j * 4]) = vv;
            }
        }
        __syncthreads();

        // O += P @ V : per-thread 8 rows x 4 d-cols
#pragma unroll 4
        for (int kk = 0; kk < 128; kk += 4) {
            float4 p4[8];
#pragma unroll
            for (int i = 0; i < 8; i++) {
                const int rl = ((i & 4) << 4) + tr * 4 + (i & 3);
                p4[i] = *reinterpret_cast<const float4*>(&Ss[rl * QT_STRIDE + kk]);
            }
#pragma unroll
            for (int e = 0; e < 4; e++) {
                float4 vv = *reinterpret_cast<const float4*>(&KV[(kk + e) * V_STRIDE + tc * 4]);
#pragma unroll
                for (int i = 0; i < 8; i++) {
                    const float p = reinterpret_cast<const float*>(&p4[i])[e];
                    o[i][0] = fmaf(p, vv.x, o[i][0]);
                    o[i][1] = fmaf(p, vv.y, o[i][1]);
                    o[i][2] = fmaf(p, vv.z, o[i][2]);
                    o[i][3] = fmaf(p, vv.w, o[i][3]);
                }
            }
        }
    }

    // finalize and store to [B,T,D]
#pragma unroll
    for (int i = 0; i < 8; i++) {
        const int rl = ((i & 4) << 4) + tr * 4 + (i & 3);
        const int t = qt * 128 + rl;
        const float inv = 1.0f / l_i[i];
        float4 ov = make_float4(o[i][0] * inv, o[i][1] * inv, o[i][2] * inv, o[i][3] * inv);
        *reinterpret_cast<float4*>(&g_ao[((long)(b * T_SEQ + t)) * DMODEL + h * HD + tc * 4]) = ov;
    }
}

// ============================================================================
extern "C" void kernel_launch(void* const* d_in, const int* in_sizes, int n_in,
                              void* d_out, int out_size)
{
    const float* x  = (const float*)d_in[0];
    const float* Wq = (const float*)d_in[1];
    const float* bq = (const float*)d_in[2];
    const float* Wk = (const float*)d_in[3];
    const float* bk = (const float*)d_in[4];
    const float* Wv = (const float*)d_in[5];
    const float* bv = (const float*)d_in[6];
    const float* Wo = (const float*)d_in[7];
    const float* bo = (const float*)d_in[8];
    float* out = (float*)d_out;

    cudaFuncSetAttribute(attn_kernel,
                         cudaFuncAttributeMaxDynamicSharedMemorySize,
                         ATTN_SMEM_BYTES);

    // QKV projections (fused, grid.z selects weight)
    qkv_kernel<<<dim3(DMODEL / 128, MROWS / 128, 3), 256>>>(x, Wq, bq, Wk, bk, Wv, bv);
    // Flash attention
    attn_kernel<<<dim3(T_SEQ / 128, NH, NB), 256, ATTN_SMEM_BYTES>>>();
    // Output projection
    out_kernel<<<dim3(DMODEL / 128, MROWS / 128), 256>>>(Wo, bo, out);
}

// round 6
// speedup vs baseline: 1.0022x; 1.0008x over previous
#include <cuda_runtime.h>

#define T_SEQ   2048
#define NB      2
#define NH      16
#define HD      64
#define DMODEL  1024
#define MROWS   (NB * T_SEQ)   // 4096

// ---- scratch (static device globals; no allocation) ----
static __device__ float g_q[NB * NH * T_SEQ * HD];     // [B,H,T,hd]
static __device__ float g_k[NB * NH * T_SEQ * HD];
static __device__ float g_v[NB * NH * T_SEQ * HD];
static __device__ float g_ao[NB * T_SEQ * DMODEL];     // [B,T,D]

// ============================================================================
// SGEMM body: C[128x128 tile] = A[M,K] @ W[K,N] + bias, M=4096, N=K=1024.
// 256 threads, 8x8 per-thread micro-tile, quad-split layout (rows/cols at
// tr*4 and 64+tr*4) so all LDS.128 are conflict-free or broadcast.
// split_heads: write to [B,H,T,hd] layout instead of [M,N].
// ============================================================================
__device__ __forceinline__ void sgemm_body(
    const float* __restrict__ A, const float* __restrict__ W,
    const float* __restrict__ bias, float* __restrict__ C,
    int split_heads)
{
    __shared__ float As[8][128];
    __shared__ float Bs[8][128];

    const int tid = threadIdx.x;
    const int m0 = blockIdx.y * 128;
    const int n0 = blockIdx.x * 128;
    const int N = DMODEL, K = DMODEL;

    const int arow = tid >> 1;          // 0..127
    const int acol = (tid & 1) << 2;    // 0 or 4
    const int brow = tid >> 5;          // 0..7
    const int bcol = (tid & 31) << 2;   // 0..124
    const int tr = tid >> 4;            // 0..15
    const int tc = tid & 15;            // 0..15

    float acc[8][8];
#pragma unroll
    for (int i = 0; i < 8; i++)
#pragma unroll
        for (int j = 0; j < 8; j++) acc[i][j] = 0.0f;

    const float* Aptr = A + (m0 + arow) * K + acol;
    const float* Wptr = W + brow * N + n0 + bcol;

    for (int k0 = 0; k0 < K; k0 += 8) {
        float4 av = *reinterpret_cast<const float4*>(Aptr + k0);
        float4 bv = *reinterpret_cast<const float4*>(Wptr + (long)k0 * N);
        __syncthreads();
        As[acol + 0][arow] = av.x;
        As[acol + 1][arow] = av.y;
        As[acol + 2][arow] = av.z;
        As[acol + 3][arow] = av.w;
        *reinterpret_cast<float4*>(&Bs[brow][bcol]) = bv;
        __syncthreads();
#pragma unroll
        for (int kk = 0; kk < 8; kk++) {
            float a[8], b[8];
            *reinterpret_cast<float4*>(&a[0]) = *reinterpret_cast<const float4*>(&As[kk][tr * 4]);
            *reinterpret_cast<float4*>(&a[4]) = *reinterpret_cast<const float4*>(&As[kk][tr * 4 + 64]);
            *reinterpret_cast<float4*>(&b[0]) = *reinterpret_cast<const float4*>(&Bs[kk][tc * 4]);
            *reinterpret_cast<float4*>(&b[4]) = *reinterpret_cast<const float4*>(&Bs[kk][tc * 4 + 64]);
#pragma unroll
            for (int i = 0; i < 8; i++)
#pragma unroll
                for (int j = 0; j < 8; j++)
                    acc[i][j] = fmaf(a[i], b[j], acc[i][j]);
        }
    }

    // epilogue: bias add + store
#pragma unroll
    for (int ih = 0; ih < 2; ih++) {
#pragma unroll
        for (int ii = 0; ii < 4; ii++) {
            const int i = ih * 4 + ii;
            const int r = m0 + ih * 64 + tr * 4 + ii;
#pragma unroll
            for (int jh = 0; jh < 2; jh++) {
                const int c = n0 + jh * 64 + tc * 4;
                float4 bb = *reinterpret_cast<const float4*>(&bias[c]);
                float4 ov;
                ov.x = acc[i][jh * 4 + 0] + bb.x;
                ov.y = acc[i][jh * 4 + 1] + bb.y;
                ov.z = acc[i][jh * 4 + 2] + bb.z;
                ov.w = acc[i][jh * 4 + 3] + bb.w;
                if (!split_heads) {
                    *reinterpret_cast<float4*>(&C[(long)r * N + c]) = ov;
                } else {
                    // r = b*T + t ; c = h*64 + d  ->  [B,H,T,hd]
                    const int b = r >> 11;
                    const int t = r & (T_SEQ - 1);
                    const int h = c >> 6;
                    const int d = c & 63;
                    const long idx = (((long)(b * NH + h) * T_SEQ + t) * HD + d);
                    *reinterpret_cast<float4*>(&C[idx]) = ov;
                }
            }
        }
    }
}

__global__ void __launch_bounds__(256, 2)
qkv_kernel(const float* __restrict__ x,
           const float* __restrict__ Wq, const float* __restrict__ bq,
           const float* __restrict__ Wk, const float* __restrict__ bk,
           const float* __restrict__ Wv, const float* __restrict__ bv)
{
    const float* W; const float* bias; float* out;
    if (blockIdx.z == 0)      { W = Wq; bias = bq; out = g_q; }
    else if (blockIdx.z == 1) { W = Wk; bias = bk; out = g_k; }
    else                      { W = Wv; bias = bv; out = g_v; }
    sgemm_body(x, W, bias, out, 1);
}

__global__ void __launch_bounds__(256, 2)
out_kernel(const float* __restrict__ Wo, const float* __restrict__ bo,
           float* __restrict__ C)
{
    sgemm_body(g_ao, Wo, bo, C, 0);
}

// ============================================================================
// Flash attention (fp32): q-tile 128, k-tile 128, online softmax.
// smem: Qt [64 d][132] (transposed, pre-scaled), KV shared buffer
//       (Kt [64][132] then V [128][68]), Ss [128][132] for P.
// ============================================================================
#define QT_STRIDE 132
#define V_STRIDE  68
#define ATTN_SMEM_FLOATS (64 * QT_STRIDE + 128 * V_STRIDE + 128 * QT_STRIDE)
#define ATTN_SMEM_BYTES  (ATTN_SMEM_FLOATS * 4)

__global__ void __launch_bounds__(256)
attn_kernel()
{
    extern __shared__ float sm[];
    float* Qt = sm;                                   // 64 x 132
    float* KV = sm + 64 * QT_STRIDE;                  // max(64x132, 128x68) = 8704
    float* Ss = sm + 64 * QT_STRIDE + 128 * V_STRIDE; // 128 x 132

    const int tid = threadIdx.x;
    const int qt = blockIdx.x;   // 0..15
    const int h  = blockIdx.y;   // 0..15
    const int b  = blockIdx.z;   // 0..1
    const int bh = b * NH + h;

    const float* qg  = g_q + ((long)bh * T_SEQ + qt * 128) * HD;
    const float* kgb = g_k + (long)bh * T_SEQ * HD;
    const float* vgb = g_v + (long)bh * T_SEQ * HD;

    // load Q tile transposed (d-major), pre-scaled by hd^-0.5
    {
        const int row = tid >> 1;
        const int dg  = (tid & 1) * 32;
#pragma unroll
        for (int j = 0; j < 8; j++) {
            float4 qv = *reinterpret_cast<const float4*>(&qg[row * HD + dg + j * 4]);
            Qt[(dg + j * 4 + 0) * QT_STRIDE + row] = qv.x * 0.125f;
            Qt[(dg + j * 4 + 1) * QT_STRIDE + row] = qv.y * 0.125f;
            Qt[(dg + j * 4 + 2) * QT_STRIDE + row] = qv.z * 0.125f;
            Qt[(dg + j * 4 + 3) * QT_STRIDE + row] = qv.w * 0.125f;
        }
    }

    const int tr = tid >> 4;   // 0..15
    const int tc = tid & 15;   // 0..15

    float m_i[8], l_i[8], o[8][4];
#pragma unroll
    for (int i = 0; i < 8; i++) {
        m_i[i] = -1e30f;
        l_i[i] = 0.0f;
#pragma unroll
        for (int j = 0; j < 4; j++) o[i][j] = 0.0f;
    }

    const int nkt = qt + 1;
    for (int kt = 0; kt < nkt; kt++) {
        __syncthreads();  // previous PV reads of KV done; Q visible (iter 0)
        // load K tile transposed into KV
        {
            const int row = tid >> 1;
            const int dg  = (tid & 1) * 32;
            const float* kg = kgb + (long)(kt * 128 + row) * HD;
#pragma unroll
            for (int j = 0; j < 8; j++) {
                float4 kv = *reinterpret_cast<const float4*>(&kg[dg + j * 4]);
                KV[(dg + j * 4 + 0) * QT_STRIDE + row] = kv.x;
                KV[(dg + j * 4 + 1) * QT_STRIDE + row] = kv.y;
                KV[(dg + j * 4 + 2) * QT_STRIDE + row] = kv.z;
                KV[(dg + j * 4 + 3) * QT_STRIDE + row] = kv.w;
            }
        }
        __syncthreads();

        // S = Q @ K^T  (128x128, micro 8x8)
        float s[8][8];
#pragma unroll
        for (int i = 0; i < 8; i++)
#pragma unroll
            for (int j = 0; j < 8; j++) s[i][j] = 0.0f;

#pragma unroll 8
        for (int kk = 0; kk < 64; kk++) {
            float a[8], bb[8];
            *reinterpret_cast<float4*>(&a[0])  = *reinterpret_cast<const float4*>(&Qt[kk * QT_STRIDE + tr * 4]);
            *reinterpret_cast<float4*>(&a[4])  = *reinterpret_cast<const float4*>(&Qt[kk * QT_STRIDE + tr * 4 + 64]);
            *reinterpret_cast<float4*>(&bb[0]) = *reinterpret_cast<const float4*>(&KV[kk * QT_STRIDE + tc * 4]);
            *reinterpret_cast<float4*>(&bb[4]) = *reinterpret_cast<const float4*>(&KV[kk * QT_STRIDE + tc * 4 + 64]);
#pragma unroll
            for (int i = 0; i < 8; i++)
#pragma unroll
                for (int j = 0; j < 8; j++)
                    s[i][j] = fmaf(a[i], bb[j], s[i][j]);
        }

        // causal mask (diagonal tile only)
        const bool diag = (kt == qt);
        const int qrow0 = qt * 128;
        const int kcol0 = kt * 128;

        float rmax[8];
#pragma unroll
        for (int i = 0; i < 8; i++) {
            float mx = -1e30f;
            const int qgidx = qrow0 + ((i & 4) << 4) + tr * 4 + (i & 3);
#pragma unroll
            for (int j = 0; j < 8; j++) {
                if (diag) {
                    const int kgidx = kcol0 + ((j & 4) << 4) + tc * 4 + (j & 3);
                    if (kgidx > qgidx) s[i][j] = -1e30f;
                }
                mx = fmaxf(mx, s[i][j]);
            }
            rmax[i] = mx;
        }
        // row reduce (16 col-threads per row, aligned half-warp groups)
#pragma unroll
        for (int off = 8; off > 0; off >>= 1)
#pragma unroll
            for (int i = 0; i < 8; i++)
                rmax[i] = fmaxf(rmax[i], __shfl_xor_sync(0xffffffffu, rmax[i], off, 16));

#pragma unroll
        for (int i = 0; i < 8; i++) {
            const float mnew  = fmaxf(m_i[i], rmax[i]);
            const float alpha = __expf(m_i[i] - mnew);
            m_i[i] = mnew;
            float rsum = 0.0f;
#pragma unroll
            for (int j = 0; j < 8; j++) {
                s[i][j] = __expf(s[i][j] - mnew);
                rsum += s[i][j];
            }
#pragma unroll
            for (int off = 8; off > 0; off >>= 1)
                rsum += __shfl_xor_sync(0xffffffffu, rsum, off, 16);
            l_i[i] = l_i[i] * alpha + rsum;
#pragma unroll
            for (int j = 0; j < 4; j++) o[i][j] *= alpha;

            const int rl = ((i & 4) << 4) + tr * 4 + (i & 3);
            *reinterpret_cast<float4*>(&Ss[rl * QT_STRIDE + tc * 4]) =
                make_float4(s[i][0], s[i][1], s[i][2], s[i][3]);
            *reinterpret_cast<float4*>(&Ss[rl * QT_STRIDE + 64 + tc * 4]) =
                make_float4(s[i][4], s[i][5], s[i][6], s[i][7]);
        }

        __syncthreads();  // S-compute reads of KV done; Ss stores done

        // load V tile into KV as [128][V_STRIDE]
        {
            const int row = tid >> 1;
            const int dg  = (tid & 1) * 32;
            const float* vg = vgb + (long)(kt * 128 + row) * HD;
#pragma unroll
            for (int j = 0; j < 8; j++) {
                float4 vv = *reinterpret_cast<const float4*>(&vg[dg + j * 4]);
                *reinterpret_cast<float4*>(&KV[row * V_STRIDE + dg + j * 4]) = vv;
            }
        }
        __syncthreads();

        // O += P @ V : per-thread 8 rows x 4 d-cols
#pragma unroll 4
        for (int kk = 0; kk < 128; kk += 4) {
            float4 p4[8];
#pragma unroll
            for (int i = 0; i < 8; i++) {
                const int rl = ((i & 4) << 4) + tr * 4 + (i & 3);
                p4[i] = *reinterpret_cast<const float4*>(&Ss[rl * QT_STRIDE + kk]);
            }
#pragma unroll
            for (int e = 0; e < 4; e++) {
                float4 vv = *reinterpret_cast<const float4*>(&KV[(kk + e) * V_STRIDE + tc * 4]);
#pragma unroll
                for (int i = 0; i < 8; i++) {
                    const float p = reinterpret_cast<const float*>(&p4[i])[e];
                    o[i][0] = fmaf(p, vv.x, o[i][0]);
                    o[i][1] = fmaf(p, vv.y, o[i][1]);
                    o[i][2] = fmaf(p, vv.z, o[i][2]);
                    o[i][3] = fmaf(p, vv.w, o[i][3]);
                }
            }
        }
    }

    // finalize and store to [B,T,D]
#pragma unroll
    for (int i = 0; i < 8; i++) {
        const int rl = ((i & 4) << 4) + tr * 4 + (i & 3);
        const int t = qt * 128 + rl;
        const float inv = 1.0f / l_i[i];
        float4 ov = make_float4(o[i][0] * inv, o[i][1] * inv, o[i][2] * inv, o[i][3] * inv);
        *reinterpret_cast<float4*>(&g_ao[((long)(b * T_SEQ + t)) * DMODEL + h * HD + tc * 4]) = ov;
    }
}

// ============================================================================
extern "C" void kernel_launch(void* const* d_in, const int* in_sizes, int n_in,
                              void* d_out, int out_size)
{
    const float* x  = (const float*)d_in[0];
    const float* Wq = (const float*)d_in[1];
    const float* bq = (const float*)d_in[2];
    const float* Wk = (const float*)d_in[3];
    const float* bk = (const float*)d_in[4];
    const float* Wv = (const float*)d_in[5];
    const float* bv = (const float*)d_in[6];
    const float* Wo = (const float*)d_in[7];
    const float* bo = (const float*)d_in[8];
    float* out = (float*)d_out;

    cudaFuncSetAttribute(attn_kernel,
                         cudaFuncAttributeMaxDynamicSharedMemorySize,
                         ATTN_SMEM_BYTES);

    // QKV projections (fused, grid.z selects weight)
    qkv_kernel<<<dim3(DMODEL / 128, MROWS / 128, 3), 256>>>(x, Wq, bq, Wk, bk, Wv, bv);
    // Flash attention
    attn_kernel<<<dim3(T_SEQ / 128, NH, NB), 256, ATTN_SMEM_BYTES>>>();
    // Output projection
    out_kernel<<<dim3(DMODEL / 128, MROWS / 128), 256>>>(Wo, bo, out);
}